// round 15
// baseline (speedup 1.0000x reference)
#include <cuda_runtime.h>
#include <cuda_bf16.h>
#include <cstdint>
#include <cstddef>

#define NN 100000
#define EE 1600000
#define CC 128
#define FPD 512
#define GG 1024
#define NL 3
#define NBLK_SCAN ((NN + 1023) / 1024)   // 98

typedef unsigned long long ull;

// ---------------- scratch (static device globals; no allocation) ------------
__device__ float g_buf0[(size_t)NN * CC];
__device__ float g_buf1[(size_t)NN * CC];
__device__ int   g_deg[NN];
__device__ int   g_rowptr[NN + 1];
__device__ int   g_cursor[NN];
__device__ int   g_colidx[EE];
__device__ int   g_part[NBLK_SCAN];
__device__ float g_wcat[(size_t)NL * 256 * CC];            // [l][k(256)][n(128)]
__device__ __nv_bfloat16 g_x1a[(size_t)NN * CC];           // bf16 split, parity 0
__device__ __nv_bfloat16 g_x2a[(size_t)NN * CC];
__device__ __nv_bfloat16 g_x1b[(size_t)NN * CC];           // bf16 split, parity 1
__device__ __nv_bfloat16 g_x2b[(size_t)NN * CC];
__device__ __nv_bfloat16 g_wfp1[(size_t)NL * FPD * CC];    // bf16 split of Wfp [f][k]
__device__ __nv_bfloat16 g_wfp2[(size_t)NL * FPD * CC];

// ---------------- f32x2 helpers ----------------------------------------------
__device__ __forceinline__ ull dup2(float x) {
    ull r;
    asm("mov.b64 %0, {%1, %1};" : "=l"(r) : "f"(x));
    return r;
}
__device__ __forceinline__ void fma2(ull& acc, ull a, ull b) {
    asm("fma.rn.f32x2 %0, %1, %2, %0;" : "+l"(acc) : "l"(a), "l"(b));
}
__device__ __forceinline__ float2 unpk2(ull v) {
    float2 r;
    asm("mov.b64 {%0, %1}, %2;" : "=f"(r.x), "=f"(r.y) : "l"(v));
    return r;
}

// ---------------- mma.sync helpers (plain sm_80+ PTX, compute_103-safe) -------
__device__ __forceinline__ uint32_t smem_u32(const void* p) {
    uint32_t a;
    asm("{ .reg .u64 t; cvta.to.shared.u64 t, %1; cvt.u32.u64 %0, t; }"
        : "=r"(a) : "l"(p));
    return a;
}
__device__ __forceinline__ void ldsm_x4(uint32_t addr, uint32_t* r) {
    asm volatile("ldmatrix.sync.aligned.m8n8.x4.shared.b16 {%0,%1,%2,%3}, [%4];"
                 : "=r"(r[0]), "=r"(r[1]), "=r"(r[2]), "=r"(r[3]) : "r"(addr));
}
__device__ __forceinline__ void mma16816(float* c, const uint32_t* a, const uint32_t* b) {
    asm volatile(
        "mma.sync.aligned.m16n8k16.row.col.f32.bf16.bf16.f32 "
        "{%0,%1,%2,%3}, {%4,%5,%6,%7}, {%8,%9}, {%0,%1,%2,%3};"
        : "+f"(c[0]), "+f"(c[1]), "+f"(c[2]), "+f"(c[3])
        : "r"(a[0]), "r"(a[1]), "r"(a[2]), "r"(a[3]), "r"(b[0]), "r"(b[1]));
}
__device__ __forceinline__ void cp16(uint32_t dst, const void* src) {
    asm volatile("cp.async.cg.shared.global [%0], [%1], 16;"
                 :: "r"(dst), "l"(src) : "memory");
}
#define CP_COMMIT() asm volatile("cp.async.commit_group;" ::: "memory")
#define CP_WAIT1()  asm volatile("cp.async.wait_group 1;" ::: "memory")
#define CP_WAIT0()  asm volatile("cp.async.wait_group 0;" ::: "memory")

// smem layout (bytes) for k_fp_mma, BM=64
#define AROWB   272
#define BROWB   80
#define OFF_A1  0
#define OFF_A2  17408
#define OFF_B   34816
#define BSTAGE  40960
#define OFF_MISC (OFF_B + 4 * BSTAGE)   // 198656
#define FP_SMEM  (OFF_MISC + 512)       // 199168

// smem layout (bytes) for k_fused_tanh (BM=64): Nt 128x68 f32, Ast 32x68, W 2x16KB
#define FT_STRIDE 68
#define FT_NT    0                      // 128*68*4 = 34816
#define FT_AST   34816                  // 32*68*4 = 8704
#define FT_W0    43520
#define FT_W1    59904
#define FT_SMEM  76288                  // occ 2: 152576 < 227KB

// ---------------- prep: weight transpose/splits --------------------------------
__global__ void k_prep(const float* __restrict__ Ws, const float* __restrict__ Wn,
                       const float* __restrict__ Wfp) {
    int i = blockIdx.x * blockDim.x + threadIdx.x;
    const int NC = NL * 256 * CC;
    const int NF = NL * FPD * CC;
    if (i < NC) {
        int l = i / (256 * CC);
        int r = i % (256 * CC);
        int k = r >> 7;
        int n = r & 127;
        float v = (k < CC) ? Ws[(size_t)l * CC * CC + n * CC + k]
                           : Wn[(size_t)l * CC * CC + n * CC + (k - CC)];
        g_wcat[i] = v;
    }
    if (i < NF) {
        float w = Wfp[i];
        __nv_bfloat16 w1 = __float2bfloat16(w);
        g_wfp1[i] = w1;
        g_wfp2[i] = __float2bfloat16(w - __bfloat162float(w1));
    }
}

__global__ void k_hist(const int* __restrict__ ei) {
    int e = blockIdx.x * blockDim.x + threadIdx.x;
    if (e < EE) atomicAdd(&g_deg[ei[e]], 1);
}

// ---------------- 2-phase multi-block exclusive scan ---------------------------
__global__ void __launch_bounds__(1024) k_scan1() {
    __shared__ int s[1024];
    int t = threadIdx.x;
    int i = blockIdx.x * 1024 + t;
    s[t] = (i < NN) ? g_deg[i] : 0;
    __syncthreads();
#pragma unroll
    for (int off = 512; off > 0; off >>= 1) {
        if (t < off) s[t] += s[t + off];
        __syncthreads();
    }
    if (t == 0) g_part[blockIdx.x] = s[0];
}

// block scan + redundant per-block scan of the 98 partials (scan2 folded in)
__global__ void __launch_bounds__(1024) k_scan3() {
    __shared__ int s[1024];
    __shared__ int sp[NBLK_SCAN];
    int t = threadIdx.x;
    if (t < NBLK_SCAN) sp[t] = g_part[t];
    int i = blockIdx.x * 1024 + t;
    int v = (i < NN) ? g_deg[i] : 0;
    s[t] = v;
    __syncthreads();
    if (t == 0) {                       // serial exclusive scan of 98 partials
        int run = 0;
#pragma unroll 7
        for (int b = 0; b < NBLK_SCAN; ++b) {
            int pv = sp[b];
            sp[b] = run;
            run += pv;
        }
    }
#pragma unroll
    for (int off = 1; off < 1024; off <<= 1) {
        int u = 0;
        if (t >= off) u = s[t - off];
        __syncthreads();
        if (t >= off) s[t] += u;
        __syncthreads();
    }
    if (i < NN) {
        int excl = s[t] - v + sp[blockIdx.x];
        g_rowptr[i] = excl;
        g_cursor[i] = excl;
    }
    if (i == 0) g_rowptr[NN] = EE;
}

__global__ void k_fill(const int* __restrict__ ei) {
    int e = blockIdx.x * blockDim.x + threadIdx.x;
    if (e < EE) {
        int r = ei[e];
        int c = ei[EE + e];
        int p = atomicAdd(&g_cursor[r], 1);
        g_colidx[p] = c;
    }
}

// ---------------- fused neigh-gather + tanh GEMM (f32x2) + bf16 split ----------
// BM=64 rows, BN=128, 256 threads, thread tile 4m x 4 col-pairs (8 cols).
// Phase 1: warp-per-node CSR gather -> Nt[k(128)][m(64)] (transposed, in smem).
// Phase 2: 8 GEMM stages (K=256); stages 0-3 A=x (reg-prefetch), 4-7 A=Nt.
__global__ void __launch_bounds__(256, 2) k_fused_tanh(
    const float* __restrict__ X, const float* __restrict__ Wc,
    const float* __restrict__ b0, const float* __restrict__ b1,
    float* __restrict__ out,
    __nv_bfloat16* __restrict__ x1, __nv_bfloat16* __restrict__ x2)
{
    extern __shared__ char tsm[];
    float* Nt  = (float*)(tsm + FT_NT);    // [k(128)][m(64)] stride FT_STRIDE
    float* Ast = (float*)(tsm + FT_AST);   // [k(32)][m(64)]  stride FT_STRIDE
    uint32_t sbase = smem_u32(tsm);
    int tid = threadIdx.x;
    int wid = tid >> 5, lane = tid & 31;
    int cg = tid & 15;    // cols cg*8 .. cg*8+7
    int rg = tid >> 4;    // rows rg*4 .. rg*4+3
    int mbase = blockIdx.x * 64;

    // W stage 0 via cp.async (group 0)
#pragma unroll
    for (int t = 0; t < 4; ++t) {
        int i4 = tid + t * 256;            // 1024 x 16B = 16KB
        int kk = i4 >> 5, n4 = i4 & 31;
        cp16(sbase + FT_W0 + i4 * 16, Wc + kk * 128 + n4 * 4);
    }
    CP_COMMIT();

    // A stage 0 register prefetch (64 rows x 32 k = 2048 elems, 8/thread)
    float aR[8];
#pragma unroll
    for (int t = 0; t < 8; ++t) {
        int idx = tid + t * 256;
        int k = idx & 31, m = idx >> 5;
        int gm = mbase + m;
        aR[t] = (gm < NN) ? X[(size_t)gm * CC + k] : 0.f;
    }

    // Phase 1: gather neighbor sums, write transposed into Nt
    const float4* X4 = reinterpret_cast<const float4*>(X);
#pragma unroll
    for (int i = 0; i < 8; ++i) {
        int ml = wid * 8 + i;              // local row 0..63
        int n = mbase + ml;
        float4 acc = make_float4(0.f, 0.f, 0.f, 0.f);
        if (n < NN) {
            int s = g_rowptr[n];
            int e = g_rowptr[n + 1];
            int p = s;
            for (; p + 3 < e; p += 4) {
                int c0 = g_colidx[p];
                int c1 = g_colidx[p + 1];
                int c2 = g_colidx[p + 2];
                int c3 = g_colidx[p + 3];
                float4 v0 = X4[(size_t)c0 * 32 + lane];
                float4 v1 = X4[(size_t)c1 * 32 + lane];
                float4 v2 = X4[(size_t)c2 * 32 + lane];
                float4 v3 = X4[(size_t)c3 * 32 + lane];
                acc.x += v0.x + v1.x + v2.x + v3.x;
                acc.y += v0.y + v1.y + v2.y + v3.y;
                acc.z += v0.z + v1.z + v2.z + v3.z;
                acc.w += v0.w + v1.w + v2.w + v3.w;
            }
            for (; p < e; ++p) {
                int c0 = g_colidx[p];
                float4 v0 = X4[(size_t)c0 * 32 + lane];
                acc.x += v0.x; acc.y += v0.y; acc.z += v0.z; acc.w += v0.w;
            }
        }
        int c = lane * 4;                  // channel base
        Nt[(c + 0) * FT_STRIDE + ml] = acc.x;
        Nt[(c + 1) * FT_STRIDE + ml] = acc.y;
        Nt[(c + 2) * FT_STRIDE + ml] = acc.z;
        Nt[(c + 3) * FT_STRIDE + ml] = acc.w;
    }
    __syncthreads();

    // Phase 2: GEMM K=256
    ull acc[4][4];
#pragma unroll
    for (int i = 0; i < 4; i++)
#pragma unroll
        for (int p = 0; p < 4; p++) acc[i][p] = 0ull;

    for (int stage = 0; stage < 8; ++stage) {
        if (stage < 4) {
            // store prefetched A regs (prior compute synced)
#pragma unroll
            for (int t = 0; t < 8; ++t) {
                int idx = tid + t * 256;
                int k = idx & 31, m = idx >> 5;
                Ast[k * FT_STRIDE + m] = aR[t];
            }
        }
        if (stage < 7) {
            int ns = stage + 1;
            if (ns < 4) {
                int kb2 = ns * 32;
#pragma unroll
                for (int t = 0; t < 8; ++t) {
                    int idx = tid + t * 256;
                    int k = idx & 31, m = idx >> 5;
                    int gm = mbase + m;
                    aR[t] = (gm < NN) ? X[(size_t)gm * CC + kb2 + k] : 0.f;
                }
            }
            uint32_t wdst = sbase + ((ns & 1) ? FT_W1 : FT_W0);
            int kb = ns * 32;
#pragma unroll
            for (int t = 0; t < 4; ++t) {
                int i4 = tid + t * 256;
                int kk = i4 >> 5, n4 = i4 & 31;
                cp16(wdst + i4 * 16, Wc + (kb + kk) * 128 + n4 * 4);
            }
            CP_COMMIT();
            CP_WAIT1();
        } else {
            CP_WAIT0();
        }
        __syncthreads();

        const float* Asrc = (stage < 4) ? Ast : &Nt[(stage - 4) * 32 * FT_STRIDE];
        const float* Wsm = (float*)(tsm + ((stage & 1) ? FT_W1 : FT_W0));
#pragma unroll
        for (int k = 0; k < 32; ++k) {
            float4 a = *reinterpret_cast<const float4*>(&Asrc[k * FT_STRIDE + rg * 4]);
            ull ad[4] = {dup2(a.x), dup2(a.y), dup2(a.z), dup2(a.w)};
            const float* wrow = &Wsm[k * 128 + cg * 8];
            ulonglong2 w0 = *reinterpret_cast<const ulonglong2*>(wrow);
            ulonglong2 w1 = *reinterpret_cast<const ulonglong2*>(wrow + 4);
            ull wp[4] = {w0.x, w0.y, w1.x, w1.y};
#pragma unroll
            for (int i = 0; i < 4; i++)
#pragma unroll
                for (int p = 0; p < 4; p++) fma2(acc[i][p], ad[i], wp[p]);
        }
        __syncthreads();
    }
#pragma unroll
    for (int p = 0; p < 4; p++) {
        int n = cg * 8 + p * 2;
        float bx = b0[n] + b1[n];
        float by = b0[n + 1] + b1[n + 1];
#pragma unroll
        for (int i = 0; i < 4; i++) {
            int gm = mbase + rg * 4 + i;
            if (gm < NN) {
                float2 v = unpk2(acc[i][p]);
                float2 o = make_float2(tanhf(v.x + bx), tanhf(v.y + by));
                *reinterpret_cast<float2*>(&out[(size_t)gm * CC + n]) = o;
                __nv_bfloat162 h1, h2;
                h1.x = __float2bfloat16(o.x);
                h1.y = __float2bfloat16(o.y);
                h2.x = __float2bfloat16(o.x - __bfloat162float(h1.x));
                h2.y = __float2bfloat16(o.y - __bfloat162float(h1.y));
                *reinterpret_cast<__nv_bfloat162*>(&x1[(size_t)gm * CC + n]) = h1;
                *reinterpret_cast<__nv_bfloat162*>(&x2[(size_t)gm * CC + n]) = h2;
            }
        }
    }
}

// ---------------- mma.sync FP GEMM + softmax + scatter --------------------------
__device__ __forceinline__ void prefetch_chunk(
    uint32_t sbase, const __nv_bfloat16* W1, const __nv_bfloat16* W2,
    int kc, int stage, int tid)
{
#pragma unroll
    for (int t = 0; t < 8; ++t) {
        int i = tid + t * 256;
        int n = i >> 2, sub = i & 3;
        uint32_t d1 = sbase + OFF_B + (stage * 2 + 0) * BSTAGE + n * BROWB + sub * 16;
        uint32_t d2 = sbase + OFF_B + (stage * 2 + 1) * BSTAGE + n * BROWB + sub * 16;
        const __nv_bfloat16* s1 = W1 + (size_t)n * CC + kc * 32 + sub * 8;
        const __nv_bfloat16* s2 = W2 + (size_t)n * CC + kc * 32 + sub * 8;
        cp16(d1, s1);
        cp16(d2, s2);
    }
    CP_COMMIT();
}

__global__ void __launch_bounds__(256, 1) k_fp_mma(
    const __nv_bfloat16* __restrict__ X1, const __nv_bfloat16* __restrict__ X2,
    const __nv_bfloat16* __restrict__ W1, const __nv_bfloat16* __restrict__ W2,
    const int* __restrict__ batch, float* __restrict__ out)
{
    extern __shared__ char sm[];
    const int tid  = threadIdx.x;
    const int wid  = tid >> 5;
    const int lane = tid & 31;
    const int mbase = blockIdx.x * 64;
    uint32_t sbase = smem_u32(sm);

    float* inv_d = (float*)(sm + OFF_MISC);
    int*   gid   = (int*)(sm + OFF_MISC + 256);

    // stage A tiles via cp.async (joins group 0 with first B prefetch)
#pragma unroll
    for (int t = 0; t < 4; ++t) {
        int i = tid + t * 256;
        int r = i >> 4, sub = i & 15;
        int gm = mbase + r;
        uint32_t d1 = sbase + OFF_A1 + r * AROWB + sub * 16;
        uint32_t d2 = sbase + OFF_A2 + r * AROWB + sub * 16;
        if (gm < NN) {
            cp16(d1, X1 + (size_t)gm * CC + sub * 8);
            cp16(d2, X2 + (size_t)gm * CC + sub * 8);
        } else {
            uint4 z = make_uint4(0u, 0u, 0u, 0u);
            *(uint4*)(sm + OFF_A1 + r * AROWB + sub * 16) = z;
            *(uint4*)(sm + OFF_A2 + r * AROWB + sub * 16) = z;
        }
    }
    if (tid < 64) {
        int gm = mbase + tid;
        gid[tid] = (gm < NN) ? batch[gm] : -1;
    }

    prefetch_chunk(sbase, W1, W2, 0, 0, tid);   // commits group 0 (A + B0)

    float c[2][16][4];
#pragma unroll
    for (int mt = 0; mt < 2; ++mt)
#pragma unroll
        for (int nt = 0; nt < 16; ++nt)
#pragma unroll
            for (int q = 0; q < 4; ++q) c[mt][nt][q] = 0.f;

    const int mb = (wid >> 2) * 32;
    const int nb = (wid & 3) * 128;
    const int arow = lane & 15;
    const int asub = (lane >> 4) * 8;
    const int brow = (lane & 7) + ((lane >> 4) & 1) * 8;
    const int bk   = ((lane >> 3) & 1) * 8;

    for (int kc = 0; kc < 4; ++kc) {
        if (kc < 3) {
            prefetch_chunk(sbase, W1, W2, kc + 1, (kc + 1) & 1, tid);
            CP_WAIT1();
        } else {
            CP_WAIT0();
        }
        __syncthreads();
        uint32_t b1base = sbase + OFF_B + ((kc & 1) * 2 + 0) * BSTAGE;
        uint32_t b2base = b1base + BSTAGE;
#pragma unroll
        for (int ks = 0; ks < 2; ++ks) {
            int kk = ks * 16;
            int kcol = kc * 32 + kk;
            uint32_t a1f[2][4], a2f[2][4];
#pragma unroll
            for (int mt = 0; mt < 2; ++mt) {
                uint32_t ao = (uint32_t)((mb + mt * 16 + arow) * AROWB + (kcol + asub) * 2);
                ldsm_x4(sbase + OFF_A1 + ao, a1f[mt]);
                ldsm_x4(sbase + OFF_A2 + ao, a2f[mt]);
            }
#pragma unroll
            for (int nt = 0; nt < 16; nt += 2) {
                uint32_t bo = (uint32_t)((nb + nt * 8 + brow) * BROWB + (kk + bk) * 2);
                uint32_t b1f[4], b2f[4];
                ldsm_x4(b1base + bo, b1f);
                ldsm_x4(b2base + bo, b2f);
#pragma unroll
                for (int mt = 0; mt < 2; ++mt) {
                    mma16816(c[mt][nt],     a1f[mt], b1f);
                    mma16816(c[mt][nt],     a2f[mt], b1f);
                    mma16816(c[mt][nt],     a1f[mt], b2f);
                    mma16816(c[mt][nt + 1], a1f[mt], b1f + 2);
                    mma16816(c[mt][nt + 1], a2f[mt], b1f + 2);
                    mma16816(c[mt][nt + 1], a1f[mt], b2f + 2);
                }
            }
        }
        __syncthreads();
    }

    float* logits = (float*)(sm + OFF_B);
#pragma unroll
    for (int mt = 0; mt < 2; ++mt)
#pragma unroll
        for (int nt = 0; nt < 16; ++nt) {
            int r0 = mb + mt * 16 + (lane >> 2);
            int c0 = nb + nt * 8 + (lane & 3) * 2;
            *(float2*)&logits[r0 * FPD + c0] = make_float2(c[mt][nt][0], c[mt][nt][1]);
            *(float2*)&logits[(r0 + 8) * FPD + c0] = make_float2(c[mt][nt][2], c[mt][nt][3]);
        }
    __syncthreads();

    for (int r = wid * 8; r < wid * 8 + 8; ++r) {
        float v[16];
        float vmax = -1e30f;
#pragma unroll
        for (int i = 0; i < 16; i++) {
            v[i] = logits[r * FPD + lane + i * 32];
            vmax = fmaxf(vmax, v[i]);
        }
#pragma unroll
        for (int o = 16; o > 0; o >>= 1)
            vmax = fmaxf(vmax, __shfl_xor_sync(0xffffffffu, vmax, o));
        float s = 0.f;
#pragma unroll
        for (int i = 0; i < 16; i++) {
            float e = __expf(v[i] - vmax);
            logits[r * FPD + lane + i * 32] = e;
            s += e;
        }
#pragma unroll
        for (int o = 16; o > 0; o >>= 1)
            s += __shfl_xor_sync(0xffffffffu, s, o);
        if (lane == 0) inv_d[r] = 1.f / s;
    }
    __syncthreads();

#pragma unroll
    for (int cc = 0; cc < 2; ++cc) {
        int col = tid + cc * 256;
        float run = 0.f;
        int gp = gid[0];
#pragma unroll 4
        for (int r = 0; r < 64; ++r) {
            int g = gid[r];
            if (g != gp) {
                if (gp >= 0) atomicAdd(&out[(size_t)gp * FPD + col], run);
                run = 0.f;
                gp = g;
            }
            if (g >= 0) run += logits[r * FPD + col] * inv_d[r];
        }
        if (gp >= 0) atomicAdd(&out[(size_t)gp * FPD + col], run);
    }
}

// ---------------- host launch -------------------------------------------------
extern "C" void kernel_launch(void* const* d_in, const int* in_sizes, int n_in,
                              void* d_out, int out_size) {
    const float* x     = (const float*)d_in[0];
    const float* Ws    = (const float*)d_in[1];
    const float* bs    = (const float*)d_in[2];
    const float* Wn    = (const float*)d_in[3];
    const float* bn    = (const float*)d_in[4];
    const float* Wfp   = (const float*)d_in[5];
    const int*   ei    = (const int*)d_in[6];
    const int*   batch = (const int*)d_in[7];
    float*       out   = (float*)d_out;

    float *buf0, *buf1, *wcat;
    int* degp;
    __nv_bfloat16 *x1a, *x2a, *x1b, *x2b, *wfp1, *wfp2;
    cudaGetSymbolAddress((void**)&buf0,  g_buf0);
    cudaGetSymbolAddress((void**)&buf1,  g_buf1);
    cudaGetSymbolAddress((void**)&degp,  g_deg);
    cudaGetSymbolAddress((void**)&wcat,  g_wcat);
    cudaGetSymbolAddress((void**)&x1a,   g_x1a);
    cudaGetSymbolAddress((void**)&x2a,   g_x2a);
    cudaGetSymbolAddress((void**)&x1b,   g_x1b);
    cudaGetSymbolAddress((void**)&x2b,   g_x2b);
    cudaGetSymbolAddress((void**)&wfp1,  g_wfp1);
    cudaGetSymbolAddress((void**)&wfp2,  g_wfp2);

    static cudaStream_t s2 = nullptr;
    static cudaEvent_t evS, evP, evT[NL], evD[NL], evF;
    if (s2 == nullptr) {
        cudaStreamCreateWithFlags(&s2, cudaStreamNonBlocking);
        cudaEventCreateWithFlags(&evS, cudaEventDisableTiming);
        cudaEventCreateWithFlags(&evP, cudaEventDisableTiming);
        for (int l = 0; l < NL; ++l) {
            cudaEventCreateWithFlags(&evT[l], cudaEventDisableTiming);
            cudaEventCreateWithFlags(&evD[l], cudaEventDisableTiming);
        }
        cudaEventCreateWithFlags(&evF, cudaEventDisableTiming);
    }

    cudaFuncSetAttribute(k_fp_mma, cudaFuncAttributeMaxDynamicSharedMemorySize,
                         FP_SMEM);
    cudaFuncSetAttribute(k_fused_tanh, cudaFuncAttributeMaxDynamicSharedMemorySize,
                         FT_SMEM);

    // memsets on the CAPTURED stream (R9/R10 lesson)
    cudaMemsetAsync(out, 0, (size_t)GG * FPD * sizeof(float));
    cudaMemsetAsync(degp, 0, (size_t)NN * sizeof(int));

    // fork s2, run weight prep there (overlaps CSR build)
    cudaEventRecord(evS, 0);
    cudaStreamWaitEvent(s2, evS, 0);
    k_prep<<<(NL * FPD * CC + 255) / 256, 256, 0, s2>>>(Ws, Wn, Wfp);
    cudaEventRecord(evP, s2);

    k_hist<<<(EE + 255) / 256, 256>>>(ei);
    k_scan1<<<NBLK_SCAN, 1024>>>();
    k_scan3<<<NBLK_SCAN, 1024>>>();
    k_fill<<<(EE + 255) / 256, 256>>>(ei);
    cudaStreamWaitEvent(0, evP, 0);   // wcat ready before fused(0)

    const float* xin = x;
    float* bufs[2] = {buf0, buf1};
    __nv_bfloat16* x1s[2] = {x1a, x1b};
    __nv_bfloat16* x2s[2] = {x2a, x2b};

    for (int l = 0; l < NL; ++l) {
        float* xout = bufs[l & 1];
        // WAR guard: fused(l) rewrites x1s/x2s[l&1], which fp(l-2) reads.
        if (l >= 2) cudaStreamWaitEvent(0, evD[l - 2], 0);
        k_fused_tanh<<<(NN + 63) / 64, 256, FT_SMEM>>>(
            xin,
            wcat + (size_t)l * 256 * CC,
            bs + (size_t)l * CC, bn + (size_t)l * CC,
            xout, x1s[l & 1], x2s[l & 1]);
        cudaEventRecord(evT[l], 0);
        cudaStreamWaitEvent(s2, evT[l], 0);
        k_fp_mma<<<(NN + 63) / 64, 256, FP_SMEM, s2>>>(
            x1s[l & 1], x2s[l & 1],
            wfp1 + (size_t)l * FPD * CC, wfp2 + (size_t)l * FPD * CC,
            batch, out);
        cudaEventRecord(evD[l], s2);
        xin = xout;
    }
    cudaEventRecord(evF, s2);
    cudaStreamWaitEvent(0, evF, 0);
}

// round 16
// speedup vs baseline: 1.1979x; 1.1979x over previous
#include <cuda_runtime.h>
#include <cuda_bf16.h>
#include <cstdint>
#include <cstddef>

#define NN 100000
#define EE 1600000
#define CC 128
#define FPD 512
#define GG 1024
#define NL 3
#define NBLK_SCAN ((NN + 1023) / 1024)   // 98

typedef unsigned long long ull;

// ---------------- scratch (static device globals; no allocation) ------------
__device__ float g_buf0[(size_t)NN * CC];
__device__ float g_buf1[(size_t)NN * CC];
__device__ float g_neigh[(size_t)NN * CC];
__device__ int   g_deg[NN];
__device__ int   g_rowptr[NN + 1];
__device__ int   g_cursor[NN];
__device__ int   g_colidx[EE];
__device__ int   g_part[NBLK_SCAN];
__device__ float g_wcat[(size_t)NL * 256 * CC];            // [l][k(256)][n(128)]
__device__ __nv_bfloat16 g_x1a[(size_t)NN * CC];           // bf16 split, parity 0
__device__ __nv_bfloat16 g_x2a[(size_t)NN * CC];
__device__ __nv_bfloat16 g_x1b[(size_t)NN * CC];           // bf16 split, parity 1
__device__ __nv_bfloat16 g_x2b[(size_t)NN * CC];
__device__ __nv_bfloat16 g_wfp1[(size_t)NL * FPD * CC];    // bf16 split of Wfp [f][k]
__device__ __nv_bfloat16 g_wfp2[(size_t)NL * FPD * CC];

// ---------------- f32x2 helpers ----------------------------------------------
__device__ __forceinline__ ull dup2(float x) {
    ull r;
    asm("mov.b64 %0, {%1, %1};" : "=l"(r) : "f"(x));
    return r;
}
__device__ __forceinline__ void fma2(ull& acc, ull a, ull b) {
    asm("fma.rn.f32x2 %0, %1, %2, %0;" : "+l"(acc) : "l"(a), "l"(b));
}
__device__ __forceinline__ float2 unpk2(ull v) {
    float2 r;
    asm("mov.b64 {%0, %1}, %2;" : "=f"(r.x), "=f"(r.y) : "l"(v));
    return r;
}

// ---------------- mma.sync helpers (plain sm_80+ PTX, compute_103-safe) -------
__device__ __forceinline__ uint32_t smem_u32(const void* p) {
    uint32_t a;
    asm("{ .reg .u64 t; cvta.to.shared.u64 t, %1; cvt.u32.u64 %0, t; }"
        : "=r"(a) : "l"(p));
    return a;
}
__device__ __forceinline__ void ldsm_x4(uint32_t addr, uint32_t* r) {
    asm volatile("ldmatrix.sync.aligned.m8n8.x4.shared.b16 {%0,%1,%2,%3}, [%4];"
                 : "=r"(r[0]), "=r"(r[1]), "=r"(r[2]), "=r"(r[3]) : "r"(addr));
}
__device__ __forceinline__ void mma16816(float* c, const uint32_t* a, const uint32_t* b) {
    asm volatile(
        "mma.sync.aligned.m16n8k16.row.col.f32.bf16.bf16.f32 "
        "{%0,%1,%2,%3}, {%4,%5,%6,%7}, {%8,%9}, {%0,%1,%2,%3};"
        : "+f"(c[0]), "+f"(c[1]), "+f"(c[2]), "+f"(c[3])
        : "r"(a[0]), "r"(a[1]), "r"(a[2]), "r"(a[3]), "r"(b[0]), "r"(b[1]));
}
__device__ __forceinline__ void cp16(uint32_t dst, const void* src) {
    asm volatile("cp.async.cg.shared.global [%0], [%1], 16;"
                 :: "r"(dst), "l"(src) : "memory");
}
#define CP_COMMIT() asm volatile("cp.async.commit_group;" ::: "memory")
#define CP_WAIT1()  asm volatile("cp.async.wait_group 1;" ::: "memory")
#define CP_WAIT0()  asm volatile("cp.async.wait_group 0;" ::: "memory")

// smem layout (bytes) for k_fp_mma, BM=64
#define AROWB   272
#define BROWB   80
#define OFF_A1  0
#define OFF_A2  17408
#define OFF_B   34816
#define BSTAGE  40960
#define OFF_MISC (OFF_B + 4 * BSTAGE)   // 198656
#define FP_SMEM  (OFF_MISC + 512)       // 199168

// smem layout (bytes) for k_gemm_tanh (dynamic)
#define ASTRIDE  132
#define AST_OFF  0                      // 32*132*4 = 16896
#define W0_OFF   16896
#define W1_OFF   (16896 + 16384)
#define TANH_SMEM (16896 + 2 * 16384)   // 49664

// ---------------- prep: weight transpose/splits --------------------------------
__global__ void k_prep(const float* __restrict__ Ws, const float* __restrict__ Wn,
                       const float* __restrict__ Wfp) {
    int i = blockIdx.x * blockDim.x + threadIdx.x;
    const int NC = NL * 256 * CC;
    const int NF = NL * FPD * CC;
    if (i < NC) {
        int l = i / (256 * CC);
        int r = i % (256 * CC);
        int k = r >> 7;
        int n = r & 127;
        float v = (k < CC) ? Ws[(size_t)l * CC * CC + n * CC + k]
                           : Wn[(size_t)l * CC * CC + n * CC + (k - CC)];
        g_wcat[i] = v;
    }
    if (i < NF) {
        float w = Wfp[i];
        __nv_bfloat16 w1 = __float2bfloat16(w);
        g_wfp1[i] = w1;
        g_wfp2[i] = __float2bfloat16(w - __bfloat162float(w1));
    }
}

__global__ void k_hist(const int* __restrict__ ei) {
    int e = blockIdx.x * blockDim.x + threadIdx.x;
    if (e < EE) atomicAdd(&g_deg[ei[e]], 1);
}

// ---------------- 2-phase multi-block exclusive scan ---------------------------
__global__ void __launch_bounds__(1024) k_scan1() {
    __shared__ int s[1024];
    int t = threadIdx.x;
    int i = blockIdx.x * 1024 + t;
    s[t] = (i < NN) ? g_deg[i] : 0;
    __syncthreads();
#pragma unroll
    for (int off = 512; off > 0; off >>= 1) {
        if (t < off) s[t] += s[t + off];
        __syncthreads();
    }
    if (t == 0) g_part[blockIdx.x] = s[0];
}

// block scan + redundant per-block scan of the 98 partials (scan2 folded in)
__global__ void __launch_bounds__(1024) k_scan3() {
    __shared__ int s[1024];
    __shared__ int sp[NBLK_SCAN];
    int t = threadIdx.x;
    if (t < NBLK_SCAN) sp[t] = g_part[t];
    int i = blockIdx.x * 1024 + t;
    int v = (i < NN) ? g_deg[i] : 0;
    s[t] = v;
    __syncthreads();
    if (t == 0) {
        int run = 0;
#pragma unroll 7
        for (int b = 0; b < NBLK_SCAN; ++b) {
            int pv = sp[b];
            sp[b] = run;
            run += pv;
        }
    }
#pragma unroll
    for (int off = 1; off < 1024; off <<= 1) {
        int u = 0;
        if (t >= off) u = s[t - off];
        __syncthreads();
        if (t >= off) s[t] += u;
        __syncthreads();
    }
    if (i < NN) {
        int excl = s[t] - v + sp[blockIdx.x];
        g_rowptr[i] = excl;
        g_cursor[i] = excl;
    }
    if (i == 0) g_rowptr[NN] = EE;
}

__global__ void k_fill(const int* __restrict__ ei) {
    int e = blockIdx.x * blockDim.x + threadIdx.x;
    if (e < EE) {
        int r = ei[e];
        int c = ei[EE + e];
        int p = atomicAdd(&g_cursor[r], 1);
        g_colidx[p] = c;
    }
}

// ---------------- neighbor sum: warp per node, MLP=4 --------------------------
__global__ void __launch_bounds__(256) k_neigh(const float* __restrict__ X) {
    int wid  = threadIdx.x >> 5;
    int lane = threadIdx.x & 31;
    int n = blockIdx.x * 8 + wid;
    if (n >= NN) return;
    int s = g_rowptr[n];
    int e = g_rowptr[n + 1];
    const float4* X4 = reinterpret_cast<const float4*>(X);
    float4 acc = make_float4(0.f, 0.f, 0.f, 0.f);
    int p = s;
    for (; p + 3 < e; p += 4) {
        int c0 = g_colidx[p];
        int c1 = g_colidx[p + 1];
        int c2 = g_colidx[p + 2];
        int c3 = g_colidx[p + 3];
        float4 v0 = X4[(size_t)c0 * 32 + lane];
        float4 v1 = X4[(size_t)c1 * 32 + lane];
        float4 v2 = X4[(size_t)c2 * 32 + lane];
        float4 v3 = X4[(size_t)c3 * 32 + lane];
        acc.x += v0.x + v1.x + v2.x + v3.x;
        acc.y += v0.y + v1.y + v2.y + v3.y;
        acc.z += v0.z + v1.z + v2.z + v3.z;
        acc.w += v0.w + v1.w + v2.w + v3.w;
    }
    for (; p < e; ++p) {
        int c0 = g_colidx[p];
        float4 v0 = X4[(size_t)c0 * 32 + lane];
        acc.x += v0.x; acc.y += v0.y; acc.z += v0.z; acc.w += v0.w;
    }
    reinterpret_cast<float4*>(g_neigh)[(size_t)n * 32 + lane] = acc;
}

// ---------------- fused tanh GEMM (f32x2) + bf16 split epilogue ----------------
// BM=128, BN=128, 256 threads, thread tile 8 rows x 4 col-pairs (8 cols).
// Pipelined: A register-prefetch (1 stage ahead) + cp.async double-buffered W.
__global__ void __launch_bounds__(256, 2) k_gemm_tanh(
    const float* __restrict__ A0, const float* __restrict__ A1,
    const float* __restrict__ Wc,
    const float* __restrict__ b0, const float* __restrict__ b1,
    float* __restrict__ out,
    __nv_bfloat16* __restrict__ x1, __nv_bfloat16* __restrict__ x2)
{
    extern __shared__ char tsm[];
    float* Ast = (float*)(tsm + AST_OFF);   // [k(32)][m(128)] stride ASTRIDE
    uint32_t sbase = smem_u32(tsm);
    int tid = threadIdx.x;
    int cg = tid & 15;
    int rg = tid >> 4;
    int mbase = blockIdx.x * 128;

    ull acc[8][4];
#pragma unroll
    for (int i = 0; i < 8; i++)
#pragma unroll
        for (int p = 0; p < 4; p++) acc[i][p] = 0ull;

    float aR[16];
#pragma unroll
    for (int t = 0; t < 16; ++t) {
        int idx = tid + t * 256;
        int k = idx & 31, m = idx >> 5;
        int gm = mbase + m;
        aR[t] = (gm < NN) ? A0[(size_t)gm * CC + k] : 0.f;
    }
#pragma unroll
    for (int t = 0; t < 4; ++t) {
        int i4 = tid + t * 256;
        int kk = i4 >> 5, n4 = i4 & 31;
        cp16(sbase + W0_OFF + i4 * 16, Wc + kk * 128 + n4 * 4);
    }
    CP_COMMIT();

    for (int stage = 0; stage < 8; ++stage) {
#pragma unroll
        for (int t = 0; t < 16; ++t) {
            int idx = tid + t * 256;
            int k = idx & 31, m = idx >> 5;
            Ast[k * ASTRIDE + m] = aR[t];
        }
        if (stage < 7) {
            int ns = stage + 1;
            const float* A = (ns < 4) ? A0 : A1;
            int kb2 = (ns & 3) * 32;
            int kb = ns * 32;
#pragma unroll
            for (int t = 0; t < 16; ++t) {
                int idx = tid + t * 256;
                int k = idx & 31, m = idx >> 5;
                int gm = mbase + m;
                aR[t] = (gm < NN) ? A[(size_t)gm * CC + kb2 + k] : 0.f;
            }
            uint32_t wdst = sbase + ((ns & 1) ? W1_OFF : W0_OFF);
#pragma unroll
            for (int t = 0; t < 4; ++t) {
                int i4 = tid + t * 256;
                int kk = i4 >> 5, n4 = i4 & 31;
                cp16(wdst + i4 * 16, Wc + (kb + kk) * 128 + n4 * 4);
            }
            CP_COMMIT();
            CP_WAIT1();
        } else {
            CP_WAIT0();
        }
        __syncthreads();

        const float* Wsm = (float*)(tsm + ((stage & 1) ? W1_OFF : W0_OFF));
#pragma unroll
        for (int k = 0; k < 32; ++k) {
            const float* arow = &Ast[k * ASTRIDE + rg * 8];
            float4 a0 = *reinterpret_cast<const float4*>(arow);
            float4 a1 = *reinterpret_cast<const float4*>(arow + 4);
            ull ad[8] = {dup2(a0.x), dup2(a0.y), dup2(a0.z), dup2(a0.w),
                         dup2(a1.x), dup2(a1.y), dup2(a1.z), dup2(a1.w)};
            const float* wrow = &Wsm[k * 128 + cg * 8];
            ulonglong2 w0 = *reinterpret_cast<const ulonglong2*>(wrow);
            ulonglong2 w1 = *reinterpret_cast<const ulonglong2*>(wrow + 4);
            ull wp[4] = {w0.x, w0.y, w1.x, w1.y};
#pragma unroll
            for (int i = 0; i < 8; i++)
#pragma unroll
                for (int p = 0; p < 4; p++) fma2(acc[i][p], ad[i], wp[p]);
        }
        __syncthreads();
    }
#pragma unroll
    for (int p = 0; p < 4; p++) {
        int n = cg * 8 + p * 2;
        float bx = b0[n] + b1[n];
        float by = b0[n + 1] + b1[n + 1];
#pragma unroll
        for (int i = 0; i < 8; i++) {
            int gm = mbase + rg * 8 + i;
            if (gm < NN) {
                float2 v = unpk2(acc[i][p]);
                float2 o = make_float2(tanhf(v.x + bx), tanhf(v.y + by));
                *reinterpret_cast<float2*>(&out[(size_t)gm * CC + n]) = o;
                __nv_bfloat162 h1, h2;
                h1.x = __float2bfloat16(o.x);
                h1.y = __float2bfloat16(o.y);
                h2.x = __float2bfloat16(o.x - __bfloat162float(h1.x));
                h2.y = __float2bfloat16(o.y - __bfloat162float(h1.y));
                *reinterpret_cast<__nv_bfloat162*>(&x1[(size_t)gm * CC + n]) = h1;
                *reinterpret_cast<__nv_bfloat162*>(&x2[(size_t)gm * CC + n]) = h2;
            }
        }
    }
}

// ---------------- mma.sync FP GEMM + softmax + scatter --------------------------
__device__ __forceinline__ void prefetch_chunk(
    uint32_t sbase, const __nv_bfloat16* W1, const __nv_bfloat16* W2,
    int kc, int stage, int tid)
{
#pragma unroll
    for (int t = 0; t < 8; ++t) {
        int i = tid + t * 256;
        int n = i >> 2, sub = i & 3;
        uint32_t d1 = sbase + OFF_B + (stage * 2 + 0) * BSTAGE + n * BROWB + sub * 16;
        uint32_t d2 = sbase + OFF_B + (stage * 2 + 1) * BSTAGE + n * BROWB + sub * 16;
        const __nv_bfloat16* s1 = W1 + (size_t)n * CC + kc * 32 + sub * 8;
        const __nv_bfloat16* s2 = W2 + (size_t)n * CC + kc * 32 + sub * 8;
        cp16(d1, s1);
        cp16(d2, s2);
    }
    CP_COMMIT();
}

__global__ void __launch_bounds__(256, 1) k_fp_mma(
    const __nv_bfloat16* __restrict__ X1, const __nv_bfloat16* __restrict__ X2,
    const __nv_bfloat16* __restrict__ W1, const __nv_bfloat16* __restrict__ W2,
    const int* __restrict__ batch, float* __restrict__ out)
{
    extern __shared__ char sm[];
    const int tid  = threadIdx.x;
    const int wid  = tid >> 5;
    const int lane = tid & 31;
    const int mbase = blockIdx.x * 64;
    uint32_t sbase = smem_u32(sm);

    float* inv_d = (float*)(sm + OFF_MISC);
    int*   gid   = (int*)(sm + OFF_MISC + 256);

    // stage A tiles via cp.async (joins group 0 with first B prefetch)
#pragma unroll
    for (int t = 0; t < 4; ++t) {
        int i = tid + t * 256;
        int r = i >> 4, sub = i & 15;
        int gm = mbase + r;
        uint32_t d1 = sbase + OFF_A1 + r * AROWB + sub * 16;
        uint32_t d2 = sbase + OFF_A2 + r * AROWB + sub * 16;
        if (gm < NN) {
            cp16(d1, X1 + (size_t)gm * CC + sub * 8);
            cp16(d2, X2 + (size_t)gm * CC + sub * 8);
        } else {
            uint4 z = make_uint4(0u, 0u, 0u, 0u);
            *(uint4*)(sm + OFF_A1 + r * AROWB + sub * 16) = z;
            *(uint4*)(sm + OFF_A2 + r * AROWB + sub * 16) = z;
        }
    }
    if (tid < 64) {
        int gm = mbase + tid;
        gid[tid] = (gm < NN) ? batch[gm] : -1;
    }

    prefetch_chunk(sbase, W1, W2, 0, 0, tid);   // commits group 0 (A + B0)

    float c[2][16][4];
#pragma unroll
    for (int mt = 0; mt < 2; ++mt)
#pragma unroll
        for (int nt = 0; nt < 16; ++nt)
#pragma unroll
            for (int q = 0; q < 4; ++q) c[mt][nt][q] = 0.f;

    const int mb = (wid >> 2) * 32;
    const int nb = (wid & 3) * 128;
    const int arow = lane & 15;
    const int asub = (lane >> 4) * 8;
    const int brow = (lane & 7) + ((lane >> 4) & 1) * 8;
    const int bk   = ((lane >> 3) & 1) * 8;

    for (int kc = 0; kc < 4; ++kc) {
        if (kc < 3) {
            prefetch_chunk(sbase, W1, W2, kc + 1, (kc + 1) & 1, tid);
            CP_WAIT1();
        } else {
            CP_WAIT0();
        }
        __syncthreads();
        uint32_t b1base = sbase + OFF_B + ((kc & 1) * 2 + 0) * BSTAGE;
        uint32_t b2base = b1base + BSTAGE;
#pragma unroll
        for (int ks = 0; ks < 2; ++ks) {
            int kk = ks * 16;
            int kcol = kc * 32 + kk;
            uint32_t a1f[2][4], a2f[2][4];
#pragma unroll
            for (int mt = 0; mt < 2; ++mt) {
                uint32_t ao = (uint32_t)((mb + mt * 16 + arow) * AROWB + (kcol + asub) * 2);
                ldsm_x4(sbase + OFF_A1 + ao, a1f[mt]);
                ldsm_x4(sbase + OFF_A2 + ao, a2f[mt]);
            }
#pragma unroll
            for (int nt = 0; nt < 16; nt += 2) {
                uint32_t bo = (uint32_t)((nb + nt * 8 + brow) * BROWB + (kk + bk) * 2);
                uint32_t b1f[4], b2f[4];
                ldsm_x4(b1base + bo, b1f);
                ldsm_x4(b2base + bo, b2f);
#pragma unroll
                for (int mt = 0; mt < 2; ++mt) {
                    mma16816(c[mt][nt],     a1f[mt], b1f);
                    mma16816(c[mt][nt],     a2f[mt], b1f);
                    mma16816(c[mt][nt],     a1f[mt], b2f);
                    mma16816(c[mt][nt + 1], a1f[mt], b1f + 2);
                    mma16816(c[mt][nt + 1], a2f[mt], b1f + 2);
                    mma16816(c[mt][nt + 1], a1f[mt], b2f + 2);
                }
            }
        }
        __syncthreads();
    }

    float* logits = (float*)(sm + OFF_B);
#pragma unroll
    for (int mt = 0; mt < 2; ++mt)
#pragma unroll
        for (int nt = 0; nt < 16; ++nt) {
            int r0 = mb + mt * 16 + (lane >> 2);
            int c0 = nb + nt * 8 + (lane & 3) * 2;
            *(float2*)&logits[r0 * FPD + c0] = make_float2(c[mt][nt][0], c[mt][nt][1]);
            *(float2*)&logits[(r0 + 8) * FPD + c0] = make_float2(c[mt][nt][2], c[mt][nt][3]);
        }
    __syncthreads();

    for (int r = wid * 8; r < wid * 8 + 8; ++r) {
        float v[16];
        float vmax = -1e30f;
#pragma unroll
        for (int i = 0; i < 16; i++) {
            v[i] = logits[r * FPD + lane + i * 32];
            vmax = fmaxf(vmax, v[i]);
        }
#pragma unroll
        for (int o = 16; o > 0; o >>= 1)
            vmax = fmaxf(vmax, __shfl_xor_sync(0xffffffffu, vmax, o));
        float s = 0.f;
#pragma unroll
        for (int i = 0; i < 16; i++) {
            float e = __expf(v[i] - vmax);
            logits[r * FPD + lane + i * 32] = e;
            s += e;
        }
#pragma unroll
        for (int o = 16; o > 0; o >>= 1)
            s += __shfl_xor_sync(0xffffffffu, s, o);
        if (lane == 0) inv_d[r] = 1.f / s;
    }
    __syncthreads();

#pragma unroll
    for (int cc = 0; cc < 2; ++cc) {
        int col = tid + cc * 256;
        float run = 0.f;
        int gp = gid[0];
#pragma unroll 4
        for (int r = 0; r < 64; ++r) {
            int g = gid[r];
            if (g != gp) {
                if (gp >= 0) atomicAdd(&out[(size_t)gp * FPD + col], run);
                run = 0.f;
                gp = g;
            }
            if (g >= 0) run += logits[r * FPD + col] * inv_d[r];
        }
        if (gp >= 0) atomicAdd(&out[(size_t)gp * FPD + col], run);
    }
}

// ---------------- host launch -------------------------------------------------
extern "C" void kernel_launch(void* const* d_in, const int* in_sizes, int n_in,
                              void* d_out, int out_size) {
    const float* x     = (const float*)d_in[0];
    const float* Ws    = (const float*)d_in[1];
    const float* bs    = (const float*)d_in[2];
    const float* Wn    = (const float*)d_in[3];
    const float* bn    = (const float*)d_in[4];
    const float* Wfp   = (const float*)d_in[5];
    const int*   ei    = (const int*)d_in[6];
    const int*   batch = (const int*)d_in[7];
    float*       out   = (float*)d_out;

    float *buf0, *buf1, *neigh, *wcat;
    int* degp;
    __nv_bfloat16 *x1a, *x2a, *x1b, *x2b, *wfp1, *wfp2;
    cudaGetSymbolAddress((void**)&buf0,  g_buf0);
    cudaGetSymbolAddress((void**)&buf1,  g_buf1);
    cudaGetSymbolAddress((void**)&neigh, g_neigh);
    cudaGetSymbolAddress((void**)&degp,  g_deg);
    cudaGetSymbolAddress((void**)&wcat,  g_wcat);
    cudaGetSymbolAddress((void**)&x1a,   g_x1a);
    cudaGetSymbolAddress((void**)&x2a,   g_x2a);
    cudaGetSymbolAddress((void**)&x1b,   g_x1b);
    cudaGetSymbolAddress((void**)&x2b,   g_x2b);
    cudaGetSymbolAddress((void**)&wfp1,  g_wfp1);
    cudaGetSymbolAddress((void**)&wfp2,  g_wfp2);

    static cudaStream_t s2 = nullptr;
    static cudaEvent_t evS, evP, evT[NL], evD[NL], evF;
    if (s2 == nullptr) {
        cudaStreamCreateWithFlags(&s2, cudaStreamNonBlocking);
        cudaEventCreateWithFlags(&evS, cudaEventDisableTiming);
        cudaEventCreateWithFlags(&evP, cudaEventDisableTiming);
        for (int l = 0; l < NL; ++l) {
            cudaEventCreateWithFlags(&evT[l], cudaEventDisableTiming);
            cudaEventCreateWithFlags(&evD[l], cudaEventDisableTiming);
        }
        cudaEventCreateWithFlags(&evF, cudaEventDisableTiming);
    }

    cudaFuncSetAttribute(k_fp_mma, cudaFuncAttributeMaxDynamicSharedMemorySize,
                         FP_SMEM);
    cudaFuncSetAttribute(k_gemm_tanh, cudaFuncAttributeMaxDynamicSharedMemorySize,
                         TANH_SMEM);

    // memsets on the CAPTURED stream (R9/R10 lesson)
    cudaMemsetAsync(out, 0, (size_t)GG * FPD * sizeof(float));
    cudaMemsetAsync(degp, 0, (size_t)NN * sizeof(int));

    // fork s2, run weight prep there (overlaps CSR build)
    cudaEventRecord(evS, 0);
    cudaStreamWaitEvent(s2, evS, 0);
    k_prep<<<(NL * FPD * CC + 255) / 256, 256, 0, s2>>>(Ws, Wn, Wfp);
    cudaEventRecord(evP, s2);

    k_hist<<<(EE + 255) / 256, 256>>>(ei);
    k_scan1<<<NBLK_SCAN, 1024>>>();
    k_scan3<<<NBLK_SCAN, 1024>>>();
    k_fill<<<(EE + 255) / 256, 256>>>(ei);
    cudaStreamWaitEvent(0, evP, 0);   // wcat ready before tanh(0)

    const float* xin = x;
    float* bufs[2] = {buf0, buf1};
    __nv_bfloat16* x1s[2] = {x1a, x1b};
    __nv_bfloat16* x2s[2] = {x2a, x2b};

    for (int l = 0; l < NL; ++l) {
        float* xout = bufs[l & 1];
        k_neigh<<<(NN + 7) / 8, 256>>>(xin);
        // WAR guard: tanh(l) rewrites x1s/x2s[l&1], which fp(l-2) reads.
        if (l >= 2) cudaStreamWaitEvent(0, evD[l - 2], 0);
        k_gemm_tanh<<<(NN + 127) / 128, 256, TANH_SMEM>>>(
            xin, neigh,
            wcat + (size_t)l * 256 * CC,
            bs + (size_t)l * CC, bn + (size_t)l * CC,
            xout, x1s[l & 1], x2s[l & 1]);
        cudaEventRecord(evT[l], 0);
        cudaStreamWaitEvent(s2, evT[l], 0);
        k_fp_mma<<<(NN + 63) / 64, 256, FP_SMEM, s2>>>(
            x1s[l & 1], x2s[l & 1],
            wfp1 + (size_t)l * FPD * CC, wfp2 + (size_t)l * FPD * CC,
            batch, out);
        cudaEventRecord(evD[l], s2);
        xin = xout;
    }
    cudaEventRecord(evF, s2);
    cudaStreamWaitEvent(0, evF, 0);
}

// round 17
// speedup vs baseline: 1.2043x; 1.0053x over previous
#include <cuda_runtime.h>
#include <cuda_bf16.h>
#include <cstdint>
#include <cstddef>

#define NN 100000
#define EE 1600000
#define CC 128
#define FPD 512
#define GG 1024
#define NL 3
#define NBLK_SCAN ((NN + 1023) / 1024)   // 98

typedef unsigned long long ull;

// ---------------- scratch (static device globals; no allocation) ------------
__device__ float g_buf0[(size_t)NN * CC];
__device__ float g_buf1[(size_t)NN * CC];
__device__ float g_neigh[(size_t)NN * CC];
__device__ int   g_deg[NN];
__device__ int   g_rowptr[NN + 1];
__device__ int   g_cursor[NN];
__device__ int   g_colidx[EE];
__device__ int   g_part[NBLK_SCAN];
__device__ float g_wcat[(size_t)NL * 256 * CC];            // [l][k(256)][n(128)]
__device__ __nv_bfloat16 g_x1a[(size_t)NN * CC];           // bf16 split, parity 0
__device__ __nv_bfloat16 g_x2a[(size_t)NN * CC];
__device__ __nv_bfloat16 g_x1b[(size_t)NN * CC];           // bf16 split, parity 1
__device__ __nv_bfloat16 g_x2b[(size_t)NN * CC];
__device__ __nv_bfloat16 g_wfp1[(size_t)NL * FPD * CC];    // bf16 split of Wfp [f][k]
__device__ __nv_bfloat16 g_wfp2[(size_t)NL * FPD * CC];

// ---------------- f32x2 helpers ----------------------------------------------
__device__ __forceinline__ ull dup2(float x) {
    ull r;
    asm("mov.b64 %0, {%1, %1};" : "=l"(r) : "f"(x));
    return r;
}
__device__ __forceinline__ void fma2(ull& acc, ull a, ull b) {
    asm("fma.rn.f32x2 %0, %1, %2, %0;" : "+l"(acc) : "l"(a), "l"(b));
}
__device__ __forceinline__ float2 unpk2(ull v) {
    float2 r;
    asm("mov.b64 {%0, %1}, %2;" : "=f"(r.x), "=f"(r.y) : "l"(v));
    return r;
}

// ---------------- mma.sync helpers (plain sm_80+ PTX, compute_103-safe) -------
__device__ __forceinline__ uint32_t smem_u32(const void* p) {
    uint32_t a;
    asm("{ .reg .u64 t; cvta.to.shared.u64 t, %1; cvt.u32.u64 %0, t; }"
        : "=r"(a) : "l"(p));
    return a;
}
__device__ __forceinline__ void ldsm_x4(uint32_t addr, uint32_t* r) {
    asm volatile("ldmatrix.sync.aligned.m8n8.x4.shared.b16 {%0,%1,%2,%3}, [%4];"
                 : "=r"(r[0]), "=r"(r[1]), "=r"(r[2]), "=r"(r[3]) : "r"(addr));
}
__device__ __forceinline__ void mma16816(float* c, const uint32_t* a, const uint32_t* b) {
    asm volatile(
        "mma.sync.aligned.m16n8k16.row.col.f32.bf16.bf16.f32 "
        "{%0,%1,%2,%3}, {%4,%5,%6,%7}, {%8,%9}, {%0,%1,%2,%3};"
        : "+f"(c[0]), "+f"(c[1]), "+f"(c[2]), "+f"(c[3])
        : "r"(a[0]), "r"(a[1]), "r"(a[2]), "r"(a[3]), "r"(b[0]), "r"(b[1]));
}
__device__ __forceinline__ void cp16(uint32_t dst, const void* src) {
    asm volatile("cp.async.cg.shared.global [%0], [%1], 16;"
                 :: "r"(dst), "l"(src) : "memory");
}
// L1-allocating variant for weight tiles (reused by many blocks per SM)
__device__ __forceinline__ void cp16ca(uint32_t dst, const void* src) {
    asm volatile("cp.async.ca.shared.global [%0], [%1], 16;"
                 :: "r"(dst), "l"(src) : "memory");
}
#define CP_COMMIT() asm volatile("cp.async.commit_group;" ::: "memory")
#define CP_WAIT1()  asm volatile("cp.async.wait_group 1;" ::: "memory")
#define CP_WAIT0()  asm volatile("cp.async.wait_group 0;" ::: "memory")

// smem layout (bytes) for k_fp_mma, BM=64
#define AROWB   272
#define BROWB   80
#define OFF_A1  0
#define OFF_A2  17408
#define OFF_B   34816
#define BSTAGE  40960
#define OFF_MISC (OFF_B + 4 * BSTAGE)   // 198656
#define FP_SMEM  (OFF_MISC + 512)       // 199168

// smem layout (bytes) for k_gemm_tanh (dynamic)
#define ASTRIDE  132
#define AST_OFF  0                      // 32*132*4 = 16896
#define W0_OFF   16896
#define W1_OFF   (16896 + 16384)
#define TANH_SMEM (16896 + 2 * 16384)   // 49664

// ---------------- prep: weight transpose/splits --------------------------------
__global__ void k_prep(const float* __restrict__ Ws, const float* __restrict__ Wn,
                       const float* __restrict__ Wfp) {
    int i = blockIdx.x * blockDim.x + threadIdx.x;
    const int NC = NL * 256 * CC;
    const int NF = NL * FPD * CC;
    if (i < NC) {
        int l = i / (256 * CC);
        int r = i % (256 * CC);
        int k = r >> 7;
        int n = r & 127;
        float v = (k < CC) ? Ws[(size_t)l * CC * CC + n * CC + k]
                           : Wn[(size_t)l * CC * CC + n * CC + (k - CC)];
        g_wcat[i] = v;
    }
    if (i < NF) {
        float w = Wfp[i];
        __nv_bfloat16 w1 = __float2bfloat16(w);
        g_wfp1[i] = w1;
        g_wfp2[i] = __float2bfloat16(w - __bfloat162float(w1));
    }
}

__global__ void k_hist(const int* __restrict__ ei) {
    int e = blockIdx.x * blockDim.x + threadIdx.x;
    if (e < EE) atomicAdd(&g_deg[ei[e]], 1);
}

// ---------------- 2-phase multi-block exclusive scan ---------------------------
__global__ void __launch_bounds__(1024) k_scan1() {
    __shared__ int s[1024];
    int t = threadIdx.x;
    int i = blockIdx.x * 1024 + t;
    s[t] = (i < NN) ? g_deg[i] : 0;
    __syncthreads();
#pragma unroll
    for (int off = 512; off > 0; off >>= 1) {
        if (t < off) s[t] += s[t + off];
        __syncthreads();
    }
    if (t == 0) g_part[blockIdx.x] = s[0];
}

__global__ void __launch_bounds__(1024) k_scan3() {
    __shared__ int s[1024];
    __shared__ int sp[NBLK_SCAN];
    int t = threadIdx.x;
    if (t < NBLK_SCAN) sp[t] = g_part[t];
    int i = blockIdx.x * 1024 + t;
    int v = (i < NN) ? g_deg[i] : 0;
    s[t] = v;
    __syncthreads();
    if (t == 0) {
        int run = 0;
#pragma unroll 7
        for (int b = 0; b < NBLK_SCAN; ++b) {
            int pv = sp[b];
            sp[b] = run;
            run += pv;
        }
    }
#pragma unroll
    for (int off = 1; off < 1024; off <<= 1) {
        int u = 0;
        if (t >= off) u = s[t - off];
        __syncthreads();
        if (t >= off) s[t] += u;
        __syncthreads();
    }
    if (i < NN) {
        int excl = s[t] - v + sp[blockIdx.x];
        g_rowptr[i] = excl;
        g_cursor[i] = excl;
    }
    if (i == 0) g_rowptr[NN] = EE;
}

__global__ void k_fill(const int* __restrict__ ei) {
    int e = blockIdx.x * blockDim.x + threadIdx.x;
    if (e < EE) {
        int r = ei[e];
        int c = ei[EE + e];
        int p = atomicAdd(&g_cursor[r], 1);
        g_colidx[p] = c;
    }
}

// ---------------- neighbor sum: warp per node, MLP=4 --------------------------
__global__ void __launch_bounds__(256) k_neigh(const float* __restrict__ X) {
    int wid  = threadIdx.x >> 5;
    int lane = threadIdx.x & 31;
    int n = blockIdx.x * 8 + wid;
    if (n >= NN) return;
    int s = g_rowptr[n];
    int e = g_rowptr[n + 1];
    const float4* X4 = reinterpret_cast<const float4*>(X);
    float4 acc = make_float4(0.f, 0.f, 0.f, 0.f);
    int p = s;
    for (; p + 3 < e; p += 4) {
        int c0 = g_colidx[p];
        int c1 = g_colidx[p + 1];
        int c2 = g_colidx[p + 2];
        int c3 = g_colidx[p + 3];
        float4 v0 = X4[(size_t)c0 * 32 + lane];
        float4 v1 = X4[(size_t)c1 * 32 + lane];
        float4 v2 = X4[(size_t)c2 * 32 + lane];
        float4 v3 = X4[(size_t)c3 * 32 + lane];
        acc.x += v0.x + v1.x + v2.x + v3.x;
        acc.y += v0.y + v1.y + v2.y + v3.y;
        acc.z += v0.z + v1.z + v2.z + v3.z;
        acc.w += v0.w + v1.w + v2.w + v3.w;
    }
    for (; p < e; ++p) {
        int c0 = g_colidx[p];
        float4 v0 = X4[(size_t)c0 * 32 + lane];
        acc.x += v0.x; acc.y += v0.y; acc.z += v0.z; acc.w += v0.w;
    }
    reinterpret_cast<float4*>(g_neigh)[(size_t)n * 32 + lane] = acc;
}

// ---------------- pipelined tanh GEMM (f32x2) + bf16 split epilogue ------------
__global__ void __launch_bounds__(256, 2) k_gemm_tanh(
    const float* __restrict__ A0, const float* __restrict__ A1,
    const float* __restrict__ Wc,
    const float* __restrict__ b0, const float* __restrict__ b1,
    float* __restrict__ out,
    __nv_bfloat16* __restrict__ x1, __nv_bfloat16* __restrict__ x2)
{
    extern __shared__ char tsm[];
    float* Ast = (float*)(tsm + AST_OFF);
    uint32_t sbase = smem_u32(tsm);
    int tid = threadIdx.x;
    int cg = tid & 15;
    int rg = tid >> 4;
    int mbase = blockIdx.x * 128;

    ull acc[8][4];
#pragma unroll
    for (int i = 0; i < 8; i++)
#pragma unroll
        for (int p = 0; p < 4; p++) acc[i][p] = 0ull;

    float aR[16];
#pragma unroll
    for (int t = 0; t < 16; ++t) {
        int idx = tid + t * 256;
        int k = idx & 31, m = idx >> 5;
        int gm = mbase + m;
        aR[t] = (gm < NN) ? A0[(size_t)gm * CC + k] : 0.f;
    }
#pragma unroll
    for (int t = 0; t < 4; ++t) {
        int i4 = tid + t * 256;
        int kk = i4 >> 5, n4 = i4 & 31;
        cp16ca(sbase + W0_OFF + i4 * 16, Wc + kk * 128 + n4 * 4);
    }
    CP_COMMIT();

    for (int stage = 0; stage < 8; ++stage) {
#pragma unroll
        for (int t = 0; t < 16; ++t) {
            int idx = tid + t * 256;
            int k = idx & 31, m = idx >> 5;
            Ast[k * ASTRIDE + m] = aR[t];
        }
        if (stage < 7) {
            int ns = stage + 1;
            const float* A = (ns < 4) ? A0 : A1;
            int kb2 = (ns & 3) * 32;
            int kb = ns * 32;
#pragma unroll
            for (int t = 0; t < 16; ++t) {
                int idx = tid + t * 256;
                int k = idx & 31, m = idx >> 5;
                int gm = mbase + m;
                aR[t] = (gm < NN) ? A[(size_t)gm * CC + kb2 + k] : 0.f;
            }
            uint32_t wdst = sbase + ((ns & 1) ? W1_OFF : W0_OFF);
#pragma unroll
            for (int t = 0; t < 4; ++t) {
                int i4 = tid + t * 256;
                int kk = i4 >> 5, n4 = i4 & 31;
                cp16ca(wdst + i4 * 16, Wc + (kb + kk) * 128 + n4 * 4);
            }
            CP_COMMIT();
            CP_WAIT1();
        } else {
            CP_WAIT0();
        }
        __syncthreads();

        const float* Wsm = (float*)(tsm + ((stage & 1) ? W1_OFF : W0_OFF));
#pragma unroll
        for (int k = 0; k < 32; ++k) {
            const float* arow = &Ast[k * ASTRIDE + rg * 8];
            float4 a0 = *reinterpret_cast<const float4*>(arow);
            float4 a1 = *reinterpret_cast<const float4*>(arow + 4);
            ull ad[8] = {dup2(a0.x), dup2(a0.y), dup2(a0.z), dup2(a0.w),
                         dup2(a1.x), dup2(a1.y), dup2(a1.z), dup2(a1.w)};
            const float* wrow = &Wsm[k * 128 + cg * 8];
            ulonglong2 w0 = *reinterpret_cast<const ulonglong2*>(wrow);
            ulonglong2 w1 = *reinterpret_cast<const ulonglong2*>(wrow + 4);
            ull wp[4] = {w0.x, w0.y, w1.x, w1.y};
#pragma unroll
            for (int i = 0; i < 8; i++)
#pragma unroll
                for (int p = 0; p < 4; p++) fma2(acc[i][p], ad[i], wp[p]);
        }
        __syncthreads();
    }
#pragma unroll
    for (int p = 0; p < 4; p++) {
        int n = cg * 8 + p * 2;
        float bx = b0[n] + b1[n];
        float by = b0[n + 1] + b1[n + 1];
#pragma unroll
        for (int i = 0; i < 8; i++) {
            int gm = mbase + rg * 8 + i;
            if (gm < NN) {
                float2 v = unpk2(acc[i][p]);
                float2 o = make_float2(tanhf(v.x + bx), tanhf(v.y + by));
                *reinterpret_cast<float2*>(&out[(size_t)gm * CC + n]) = o;
                __nv_bfloat162 h1, h2;
                h1.x = __float2bfloat16(o.x);
                h1.y = __float2bfloat16(o.y);
                h2.x = __float2bfloat16(o.x - __bfloat162float(h1.x));
                h2.y = __float2bfloat16(o.y - __bfloat162float(h1.y));
                *reinterpret_cast<__nv_bfloat162*>(&x1[(size_t)gm * CC + n]) = h1;
                *reinterpret_cast<__nv_bfloat162*>(&x2[(size_t)gm * CC + n]) = h2;
            }
        }
    }
}

// ---------------- mma.sync FP GEMM + softmax + scatter --------------------------
__device__ __forceinline__ void prefetch_chunk(
    uint32_t sbase, const __nv_bfloat16* W1, const __nv_bfloat16* W2,
    int kc, int stage, int tid)
{
#pragma unroll
    for (int t = 0; t < 8; ++t) {
        int i = tid + t * 256;
        int n = i >> 2, sub = i & 3;
        uint32_t d1 = sbase + OFF_B + (stage * 2 + 0) * BSTAGE + n * BROWB + sub * 16;
        uint32_t d2 = sbase + OFF_B + (stage * 2 + 1) * BSTAGE + n * BROWB + sub * 16;
        const __nv_bfloat16* s1 = W1 + (size_t)n * CC + kc * 32 + sub * 8;
        const __nv_bfloat16* s2 = W2 + (size_t)n * CC + kc * 32 + sub * 8;
        cp16ca(d1, s1);
        cp16ca(d2, s2);
    }
    CP_COMMIT();
}

__global__ void __launch_bounds__(256, 1) k_fp_mma(
    const __nv_bfloat16* __restrict__ X1, const __nv_bfloat16* __restrict__ X2,
    const __nv_bfloat16* __restrict__ W1, const __nv_bfloat16* __restrict__ W2,
    const int* __restrict__ batch, float* __restrict__ out)
{
    extern __shared__ char sm[];
    const int tid  = threadIdx.x;
    const int wid  = tid >> 5;
    const int lane = tid & 31;
    const int mbase = blockIdx.x * 64;
    uint32_t sbase = smem_u32(sm);

    float* inv_d = (float*)(sm + OFF_MISC);
    int*   gid   = (int*)(sm + OFF_MISC + 256);

#pragma unroll
    for (int t = 0; t < 4; ++t) {
        int i = tid + t * 256;
        int r = i >> 4, sub = i & 15;
        int gm = mbase + r;
        uint32_t d1 = sbase + OFF_A1 + r * AROWB + sub * 16;
        uint32_t d2 = sbase + OFF_A2 + r * AROWB + sub * 16;
        if (gm < NN) {
            cp16(d1, X1 + (size_t)gm * CC + sub * 8);
            cp16(d2, X2 + (size_t)gm * CC + sub * 8);
        } else {
            uint4 z = make_uint4(0u, 0u, 0u, 0u);
            *(uint4*)(sm + OFF_A1 + r * AROWB + sub * 16) = z;
            *(uint4*)(sm + OFF_A2 + r * AROWB + sub * 16) = z;
        }
    }
    if (tid < 64) {
        int gm = mbase + tid;
        gid[tid] = (gm < NN) ? batch[gm] : -1;
    }

    prefetch_chunk(sbase, W1, W2, 0, 0, tid);

    float c[2][16][4];
#pragma unroll
    for (int mt = 0; mt < 2; ++mt)
#pragma unroll
        for (int nt = 0; nt < 16; ++nt)
#pragma unroll
            for (int q = 0; q < 4; ++q) c[mt][nt][q] = 0.f;

    const int mb = (wid >> 2) * 32;
    const int nb = (wid & 3) * 128;
    const int arow = lane & 15;
    const int asub = (lane >> 4) * 8;
    const int brow = (lane & 7) + ((lane >> 4) & 1) * 8;
    const int bk   = ((lane >> 3) & 1) * 8;

    for (int kc = 0; kc < 4; ++kc) {
        if (kc < 3) {
            prefetch_chunk(sbase, W1, W2, kc + 1, (kc + 1) & 1, tid);
            CP_WAIT1();
        } else {
            CP_WAIT0();
        }
        __syncthreads();
        uint32_t b1base = sbase + OFF_B + ((kc & 1) * 2 + 0) * BSTAGE;
        uint32_t b2base = b1base + BSTAGE;
#pragma unroll
        for (int ks = 0; ks < 2; ++ks) {
            int kk = ks * 16;
            int kcol = kc * 32 + kk;
            uint32_t a1f[2][4], a2f[2][4];
#pragma unroll
            for (int mt = 0; mt < 2; ++mt) {
                uint32_t ao = (uint32_t)((mb + mt * 16 + arow) * AROWB + (kcol + asub) * 2);
                ldsm_x4(sbase + OFF_A1 + ao, a1f[mt]);
                ldsm_x4(sbase + OFF_A2 + ao, a2f[mt]);
            }
#pragma unroll
            for (int nt = 0; nt < 16; nt += 2) {
                uint32_t bo = (uint32_t)((nb + nt * 8 + brow) * BROWB + (kk + bk) * 2);
                uint32_t b1f[4], b2f[4];
                ldsm_x4(b1base + bo, b1f);
                ldsm_x4(b2base + bo, b2f);
#pragma unroll
                for (int mt = 0; mt < 2; ++mt) {
                    mma16816(c[mt][nt],     a1f[mt], b1f);
                    mma16816(c[mt][nt],     a2f[mt], b1f);
                    mma16816(c[mt][nt],     a1f[mt], b2f);
                    mma16816(c[mt][nt + 1], a1f[mt], b1f + 2);
                    mma16816(c[mt][nt + 1], a2f[mt], b1f + 2);
                    mma16816(c[mt][nt + 1], a1f[mt], b2f + 2);
                }
            }
        }
        __syncthreads();
    }

    float* logits = (float*)(sm + OFF_B);
#pragma unroll
    for (int mt = 0; mt < 2; ++mt)
#pragma unroll
        for (int nt = 0; nt < 16; ++nt) {
            int r0 = mb + mt * 16 + (lane >> 2);
            int c0 = nb + nt * 8 + (lane & 3) * 2;
            *(float2*)&logits[r0 * FPD + c0] = make_float2(c[mt][nt][0], c[mt][nt][1]);
            *(float2*)&logits[(r0 + 8) * FPD + c0] = make_float2(c[mt][nt][2], c[mt][nt][3]);
        }
    __syncthreads();

    for (int r = wid * 8; r < wid * 8 + 8; ++r) {
        float v[16];
        float vmax = -1e30f;
#pragma unroll
        for (int i = 0; i < 16; i++) {
            v[i] = logits[r * FPD + lane + i * 32];
            vmax = fmaxf(vmax, v[i]);
        }
#pragma unroll
        for (int o = 16; o > 0; o >>= 1)
            vmax = fmaxf(vmax, __shfl_xor_sync(0xffffffffu, vmax, o));
        float s = 0.f;
#pragma unroll
        for (int i = 0; i < 16; i++) {
            float e = __expf(v[i] - vmax);
            logits[r * FPD + lane + i * 32] = e;
            s += e;
        }
#pragma unroll
        for (int o = 16; o > 0; o >>= 1)
            s += __shfl_xor_sync(0xffffffffu, s, o);
        if (lane == 0) inv_d[r] = 1.f / s;
    }
    __syncthreads();

#pragma unroll
    for (int cc = 0; cc < 2; ++cc) {
        int col = tid + cc * 256;
        float run = 0.f;
        int gp = gid[0];
#pragma unroll 4
        for (int r = 0; r < 64; ++r) {
            int g = gid[r];
            if (g != gp) {
                if (gp >= 0) atomicAdd(&out[(size_t)gp * FPD + col], run);
                run = 0.f;
                gp = g;
            }
            if (g >= 0) run += logits[r * FPD + col] * inv_d[r];
        }
        if (gp >= 0) atomicAdd(&out[(size_t)gp * FPD + col], run);
    }
}

// ---------------- host launch -------------------------------------------------
extern "C" void kernel_launch(void* const* d_in, const int* in_sizes, int n_in,
                              void* d_out, int out_size) {
    const float* x     = (const float*)d_in[0];
    const float* Ws    = (const float*)d_in[1];
    const float* bs    = (const float*)d_in[2];
    const float* Wn    = (const float*)d_in[3];
    const float* bn    = (const float*)d_in[4];
    const float* Wfp   = (const float*)d_in[5];
    const int*   ei    = (const int*)d_in[6];
    const int*   batch = (const int*)d_in[7];
    float*       out   = (float*)d_out;

    float *buf0, *buf1, *neigh, *wcat;
    int* degp;
    __nv_bfloat16 *x1a, *x2a, *x1b, *x2b, *wfp1, *wfp2;
    cudaGetSymbolAddress((void**)&buf0,  g_buf0);
    cudaGetSymbolAddress((void**)&buf1,  g_buf1);
    cudaGetSymbolAddress((void**)&neigh, g_neigh);
    cudaGetSymbolAddress((void**)&degp,  g_deg);
    cudaGetSymbolAddress((void**)&wcat,  g_wcat);
    cudaGetSymbolAddress((void**)&x1a,   g_x1a);
    cudaGetSymbolAddress((void**)&x2a,   g_x2a);
    cudaGetSymbolAddress((void**)&x1b,   g_x1b);
    cudaGetSymbolAddress((void**)&x2b,   g_x2b);
    cudaGetSymbolAddress((void**)&wfp1,  g_wfp1);
    cudaGetSymbolAddress((void**)&wfp2,  g_wfp2);

    static cudaStream_t s2 = nullptr;
    static cudaEvent_t evS, evP, evT[NL], evD[NL], evF;
    if (s2 == nullptr) {
        cudaStreamCreateWithFlags(&s2, cudaStreamNonBlocking);
        cudaEventCreateWithFlags(&evS, cudaEventDisableTiming);
        cudaEventCreateWithFlags(&evP, cudaEventDisableTiming);
        for (int l = 0; l < NL; ++l) {
            cudaEventCreateWithFlags(&evT[l], cudaEventDisableTiming);
            cudaEventCreateWithFlags(&evD[l], cudaEventDisableTiming);
        }
        cudaEventCreateWithFlags(&evF, cudaEventDisableTiming);
    }

    cudaFuncSetAttribute(k_fp_mma, cudaFuncAttributeMaxDynamicSharedMemorySize,
                         FP_SMEM);
    cudaFuncSetAttribute(k_gemm_tanh, cudaFuncAttributeMaxDynamicSharedMemorySize,
                         TANH_SMEM);

    cudaMemsetAsync(degp, 0, (size_t)NN * sizeof(int));

    // fork s2, run weight prep there (overlaps CSR build)
    cudaEventRecord(evS, 0);
    cudaStreamWaitEvent(s2, evS, 0);
    k_prep<<<(NL * FPD * CC + 255) / 256, 256, 0, s2>>>(Ws, Wn, Wfp);
    cudaEventRecord(evP, s2);

    k_hist<<<(EE + 255) / 256, 256>>>(ei);
    k_scan1<<<NBLK_SCAN, 1024>>>();
    k_scan3<<<NBLK_SCAN, 1024>>>();
    k_fill<<<(EE + 255) / 256, 256>>>(ei);
    cudaStreamWaitEvent(0, evP, 0);   // wcat ready before tanh(0)

    const float* xin = x;
    float* bufs[2] = {buf0, buf1};
    __nv_bfloat16* x1s[2] = {x1a, x1b};
    __nv_bfloat16* x2s[2] = {x2a, x2b};

    for (int l = 0; l < NL; ++l) {
        float* xout = bufs[l & 1];
        k_neigh<<<(NN + 7) / 8, 256>>>(xin);
        if (l == 0) {
            // zero out here (captured stream 0; ordered before fp(0) via evT)
            cudaMemsetAsync(out, 0, (size_t)GG * FPD * sizeof(float));
        }
        // WAR guard: tanh(l) rewrites x1s/x2s[l&1], which fp(l-2) reads.
        if (l >= 2) cudaStreamWaitEvent(0, evD[l - 2], 0);
        k_gemm_tanh<<<(NN + 127) / 128, 256, TANH_SMEM>>>(
            xin, neigh,
            wcat + (size_t)l * 256 * CC,
            bs + (size_t)l * CC, bn + (size_t)l * CC,
            xout, x1s[l & 1], x2s[l & 1]);
        cudaEventRecord(evT[l], 0);
        cudaStreamWaitEvent(s2, evT[l], 0);
        k_fp_mma<<<(NN + 63) / 64, 256, FP_SMEM, s2>>>(
            x1s[l & 1], x2s[l & 1],
            wfp1 + (size_t)l * FPD * CC, wfp2 + (size_t)l * FPD * CC,
            batch, out);
        cudaEventRecord(evD[l], s2);
        xin = xout;
    }
    cudaEventRecord(evF, s2);
    cudaStreamWaitEvent(0, evF, 0);
}